// round 9
// baseline (speedup 1.0000x reference)
#include <cuda_runtime.h>
#include <cuda_bf16.h>
#include <cstdint>
#include <math.h>

#define S 2048
#define D 2048
#define H 16
#define HD 128
#define FFI 8192
#define EPS 1e-5f
#define QKVN 6144
#define W13N 16384

// ---------------------------------------------------------------------------
// Static device scratch
// ---------------------------------------------------------------------------
__device__ float g_qkv[S * QKVN];     // [S, 6144] = Q | K | V (fp32, pre-rope)
__device__ float g_x1[S * D];

__device__ __nv_bfloat16 g_nx_hi[S * D],  g_nx_lo[S * D];
__device__ __nv_bfloat16 g_ao_hi[S * D],  g_ao_lo[S * D];
__device__ __nv_bfloat16 g_g_hi[S * FFI], g_g_lo[S * FFI];

// roped + split Q/K and split V, [S, D] bf16
__device__ __nv_bfloat16 g_q_hi[S * D], g_q_lo[S * D];
__device__ __nv_bfloat16 g_k_hi[S * D], g_k_lo[S * D];
__device__ __nv_bfloat16 g_v_hi[S * D], g_v_lo[S * D];

// packed transposed+split weights, [N, K] bf16
__device__ __nv_bfloat16 g_wqkvT_hi[QKVN * D], g_wqkvT_lo[QKVN * D];
__device__ __nv_bfloat16 g_woT_hi[D * D],      g_woT_lo[D * D];
__device__ __nv_bfloat16 g_w13T_hi[W13N * D],  g_w13T_lo[W13N * D];
__device__ __nv_bfloat16 g_w2T_hi[D * FFI],    g_w2T_lo[D * FFI];

// ---------------------------------------------------------------------------
// PTX helpers (baseline sm_80+, compile for compute_103)
// ---------------------------------------------------------------------------
__device__ __forceinline__ uint32_t smem_u32(const void* p) {
    uint32_t a;
    asm("{ .reg .u64 t; cvta.to.shared.u64 t, %1; cvt.u32.u64 %0, t; }"
        : "=r"(a) : "l"(p));
    return a;
}
#define CP_ASYNC16(dst, src) \
    asm volatile("cp.async.cg.shared.global [%0], [%1], 16;" \
                 :: "r"(dst), "l"(src) : "memory")
#define CP_COMMIT() asm volatile("cp.async.commit_group;" ::: "memory")
#define CP_WAIT(n)  asm volatile("cp.async.wait_group %0;" :: "n"(n) : "memory")

#define LDSM_X4(r, addr) \
    asm volatile("ldmatrix.sync.aligned.m8n8.x4.shared.b16 {%0,%1,%2,%3}, [%4];" \
        : "=r"((r)[0]), "=r"((r)[1]), "=r"((r)[2]), "=r"((r)[3]) : "r"(addr))

#define LDSM_X4_T(r, addr) \
    asm volatile("ldmatrix.sync.aligned.m8n8.x4.trans.shared.b16 {%0,%1,%2,%3}, [%4];" \
        : "=r"((r)[0]), "=r"((r)[1]), "=r"((r)[2]), "=r"((r)[3]) : "r"(addr))

#define MMA_BF16(c, a, b0, b1) \
    asm volatile("mma.sync.aligned.m16n8k16.row.col.f32.bf16.bf16.f32 " \
        "{%0,%1,%2,%3}, {%4,%5,%6,%7}, {%8,%9}, {%0,%1,%2,%3};" \
        : "+f"((c)[0]), "+f"((c)[1]), "+f"((c)[2]), "+f"((c)[3]) \
        : "r"((a)[0]), "r"((a)[1]), "r"((a)[2]), "r"((a)[3]), "r"(b0), "r"(b1))

// ---------------------------------------------------------------------------
// fp32 -> bf16 hi/lo split helpers
// ---------------------------------------------------------------------------
__device__ __forceinline__ void split1(float x, __nv_bfloat16& h, __nv_bfloat16& l) {
    h = __float2bfloat16_rn(x);
    l = __float2bfloat16_rn(x - __bfloat162float(h));
}
__device__ __forceinline__ uint32_t pack_bf16(float a, float b) {
    __nv_bfloat162 t;
    t.x = __float2bfloat16_rn(a);
    t.y = __float2bfloat16_rn(b);
    return *reinterpret_cast<uint32_t*>(&t);
}
__device__ __forceinline__ void split_store4(__nv_bfloat16* hi, __nv_bfloat16* lo,
                                             size_t idx, float4 y) {
    __nv_bfloat16 h0, h1, h2, h3, l0, l1, l2, l3;
    split1(y.x, h0, l0); split1(y.y, h1, l1);
    split1(y.z, h2, l2); split1(y.w, h3, l3);
    ushort4 hv = make_ushort4(__bfloat16_as_ushort(h0), __bfloat16_as_ushort(h1),
                              __bfloat16_as_ushort(h2), __bfloat16_as_ushort(h3));
    ushort4 lv = make_ushort4(__bfloat16_as_ushort(l0), __bfloat16_as_ushort(l1),
                              __bfloat16_as_ushort(l2), __bfloat16_as_ushort(l3));
    *reinterpret_cast<ushort4*>(hi + idx) = hv;
    *reinterpret_cast<ushort4*>(lo + idx) = lv;
}
__device__ __forceinline__ void split_store1(__nv_bfloat16* hi, __nv_bfloat16* lo,
                                             size_t idx, float v) {
    __nv_bfloat16 h, l;
    split1(v, h, l);
    hi[idx] = h; lo[idx] = l;
}

// ---------------------------------------------------------------------------
// Fused QKV weight transpose + split: blockIdx.z selects wq/wk/wv
// in [K,N] fp32 -> out rows [z*D .. z*D+N) of [QKVN, K] bf16 hi/lo
// ---------------------------------------------------------------------------
__global__ __launch_bounds__(256) void transpose_qkv_kernel(
    const float* __restrict__ wq, const float* __restrict__ wk,
    const float* __restrict__ wv,
    __nv_bfloat16* __restrict__ ohi, __nv_bfloat16* __restrict__ olo)
{
    __shared__ float t[32][33];
    const float* in = (blockIdx.z == 0) ? wq : (blockIdx.z == 1) ? wk : wv;
    const size_t obase = (size_t)blockIdx.z * D * D;
    int n0 = blockIdx.x * 32, k0 = blockIdx.y * 32;
    int tx = threadIdx.x, ty = threadIdx.y;
    #pragma unroll
    for (int j = 0; j < 4; j++)
        t[ty + 8 * j][tx] = in[(size_t)(k0 + ty + 8 * j) * D + n0 + tx];
    __syncthreads();
    #pragma unroll
    for (int j = 0; j < 4; j++) {
        float v = t[tx][ty + 8 * j];
        size_t o = obase + (size_t)(n0 + ty + 8 * j) * D + k0 + tx;
        __nv_bfloat16 h, l;
        split1(v, h, l);
        ohi[o] = h; olo[o] = l;
    }
}

// ---------------------------------------------------------------------------
// Generic weight transpose + split (remap 1/2 = w1/w3 32-col interleave)
// ---------------------------------------------------------------------------
__global__ __launch_bounds__(256) void transpose_split_kernel(
    const float* __restrict__ in, __nv_bfloat16* __restrict__ ohi,
    __nv_bfloat16* __restrict__ olo, int K, int N, int remap)
{
    __shared__ float t[32][33];
    int n0 = blockIdx.x * 32, k0 = blockIdx.y * 32;
    int tx = threadIdx.x, ty = threadIdx.y;
    #pragma unroll
    for (int j = 0; j < 4; j++)
        t[ty + 8 * j][tx] = in[(size_t)(k0 + ty + 8 * j) * N + n0 + tx];
    __syncthreads();
    #pragma unroll
    for (int j = 0; j < 4; j++) {
        float v = t[tx][ty + 8 * j];
        int n = n0 + ty + 8 * j;
        int outrow = (remap == 0) ? n
                   : ((n >> 5) * 64 + (n & 31) + ((remap == 2) ? 32 : 0));
        size_t o = (size_t)outrow * K + k0 + tx;
        __nv_bfloat16 h, l;
        split1(v, h, l);
        ohi[o] = h; olo[o] = l;
    }
}

// ---------------------------------------------------------------------------
// RMSNorm with split bf16 output
// ---------------------------------------------------------------------------
__global__ __launch_bounds__(256) void rmsnorm_split_kernel(
    const float* __restrict__ X, const float* __restrict__ W,
    __nv_bfloat16* __restrict__ Yhi, __nv_bfloat16* __restrict__ Ylo)
{
    int row = blockIdx.x;
    const float4* x4 = (const float4*)(X + (size_t)row * D);
    const float4* w4 = (const float4*)W;

    float ss = 0.f;
    #pragma unroll 2
    for (int i = threadIdx.x; i < D / 4; i += 256) {
        float4 v = x4[i];
        ss += v.x * v.x + v.y * v.y + v.z * v.z + v.w * v.w;
    }
    #pragma unroll
    for (int o = 16; o; o >>= 1) ss += __shfl_xor_sync(0xffffffffu, ss, o);
    __shared__ float red[8];
    __shared__ float s_inv;
    if ((threadIdx.x & 31) == 0) red[threadIdx.x >> 5] = ss;
    __syncthreads();
    if (threadIdx.x == 0) {
        float t = red[0] + red[1] + red[2] + red[3] + red[4] + red[5] + red[6] + red[7];
        s_inv = rsqrtf(t / (float)D + EPS);
    }
    __syncthreads();
    float inv = s_inv;
    #pragma unroll 2
    for (int i = threadIdx.x; i < D / 4; i += 256) {
        float4 v = x4[i];
        float4 w = w4[i];
        float4 y = make_float4(w.x * (v.x * inv), w.y * (v.y * inv),
                               w.z * (v.z * inv), w.w * (v.w * inv));
        split_store4(Yhi, Ylo, (size_t)row * D + i * 4, y);
    }
}

// ---------------------------------------------------------------------------
// RoPE + split: fp32 packed QKV -> bf16 hi/lo Q(roped), K(roped), V
// ---------------------------------------------------------------------------
__global__ __launch_bounds__(256) void rope_split_kernel(
    const float* __restrict__ QKV,
    const float* __restrict__ cosb, const float* __restrict__ sinb,
    __nv_bfloat16* __restrict__ qh, __nv_bfloat16* __restrict__ ql,
    __nv_bfloat16* __restrict__ kh, __nv_bfloat16* __restrict__ kl,
    __nv_bfloat16* __restrict__ vh, __nv_bfloat16* __restrict__ vl)
{
    int idx = blockIdx.x * blockDim.x + threadIdx.x;
    int d = idx & 63;
    int h = (idx >> 6) & (H - 1);
    int s = idx >> 10;
    size_t ib = (size_t)s * QKVN + (size_t)h * HD;
    size_t ob = (size_t)s * D + (size_t)h * HD;
    float c = cosb[s * HD + d];
    float sn = sinb[s * HD + d];

    float q0 = QKV[ib + d], q1 = QKV[ib + d + 64];
    split_store1(qh, ql, ob + d,      q0 * c - q1 * sn);
    split_store1(qh, ql, ob + d + 64, q1 * c + q0 * sn);

    float k0 = QKV[ib + D + d], k1 = QKV[ib + D + d + 64];
    split_store1(kh, kl, ob + d,      k0 * c - k1 * sn);
    split_store1(kh, kl, ob + d + 64, k1 * c + k0 * sn);

    float v0 = QKV[ib + 2 * D + d], v1 = QKV[ib + 2 * D + d + 64];
    split_store1(vh, vl, ob + d,      v0);
    split_store1(vh, vl, ob + d + 64, v1);
}

// ---------------------------------------------------------------------------
// HMMA bf16x3 GEMM + L2 wave swizzle (group of 4 N-tiles)
// ---------------------------------------------------------------------------
constexpr int A_TILE = 128 * 40 * 2;
constexpr int B_TILE = 256 * 40 * 2;
constexpr int STAGE  = 2 * A_TILE + 2 * B_TILE;
constexpr int GEMM_SMEM = 3 * STAGE;

__global__ __launch_bounds__(256, 1) void gemm3_kernel(
    const __nv_bfloat16* __restrict__ Ahi, const __nv_bfloat16* __restrict__ Alo,
    const __nv_bfloat16* __restrict__ Bhi, const __nv_bfloat16* __restrict__ Blo,
    const float* __restrict__ R, float* __restrict__ C,
    __nv_bfloat16* __restrict__ Ghi, __nv_bfloat16* __restrict__ Glo,
    int N, int K, int mode)
{
    extern __shared__ __align__(1024) char smem[];
    const uint32_t sb = smem_u32(smem);
    const int tid = threadIdx.x;
    const int warp = tid >> 5, lane = tid & 31;
    const int wm = warp >> 2, wn = warp & 3;

    const int lin = blockIdx.y * gridDim.x + blockIdx.x;
    const int gsz = 4 * gridDim.y;
    const int grp = lin / gsz, within = lin % gsz;
    const int m0 = (within >> 2) * 128;
    const int n0 = (grp * 4 + (within & 3)) * 256;

    auto load_stage = [&](int st, int k0) {
        const uint32_t base = sb + st * STAGE;
        #pragma unroll
        for (int i = 0; i < 4; i++) {
            int ch = tid + (i << 8);
            int sp = ch >> 9, row = (ch >> 2) & 127, c = ch & 3;
            const __nv_bfloat16* src = sp ? Alo : Ahi;
            CP_ASYNC16(base + sp * A_TILE + row * 80 + c * 16,
                       src + (size_t)(m0 + row) * K + k0 + c * 8);
        }
        #pragma unroll
        for (int i = 0; i < 8; i++) {
            int ch = tid + (i << 8);
            int sp = ch >> 10, row = (ch >> 2) & 255, c = ch & 3;
            const __nv_bfloat16* src = sp ? Blo : Bhi;
            CP_ASYNC16(base + 2 * A_TILE + sp * B_TILE + row * 80 + c * 16,
                       src + (size_t)(n0 + row) * K + k0 + c * 8);
        }
    };

    float c[4][8][4];
    #pragma unroll
    for (int i = 0; i < 4; i++)
        #pragma unroll
        for (int j = 0; j < 8; j++)
            #pragma unroll
            for (int q = 0; q < 4; q++) c[i][j][q] = 0.f;

    const int a_row = wm * 64 + (lane & 15);
    const int a_kad = (lane >> 4) << 3;
    const int b_row = wn * 64 + (lane & 7) + ((lane & 16) >> 1);
    const int b_kad = (lane & 8);

    const int nc = K >> 5;
    load_stage(0, 0);
    CP_COMMIT();
    load_stage(1, 32);
    CP_COMMIT();

    for (int ci = 0; ci < nc; ci++) {
        if (ci == nc - 1) { CP_WAIT(0); } else { CP_WAIT(1); }
        __syncthreads();
        if (ci + 2 < nc) { load_stage((ci + 2) % 3, (ci + 2) << 5); CP_COMMIT(); }

        const uint32_t base = sb + (ci % 3) * STAGE;
        const uint32_t aH = base, aL = base + A_TILE;
        const uint32_t bH = base + 2 * A_TILE, bL = bH + B_TILE;

        #pragma unroll
        for (int kk = 0; kk < 32; kk += 16) {
            uint32_t ah[4][4], bh[4][4], bl[4][4];
            const uint32_t akoff = (uint32_t)((kk + a_kad) * 2);
            const uint32_t bkoff = (uint32_t)((kk + b_kad) * 2);
            #pragma unroll
            for (int mi = 0; mi < 4; mi++)
                LDSM_X4(ah[mi], aH + (a_row + mi * 16) * 80 + akoff);
            #pragma unroll
            for (int nj = 0; nj < 4; nj++) {
                LDSM_X4(bh[nj], bH + (b_row + nj * 16) * 80 + bkoff);
                LDSM_X4(bl[nj], bL + (b_row + nj * 16) * 80 + bkoff);
            }
            #pragma unroll
            for (int mi = 0; mi < 4; mi++)
                #pragma unroll
                for (int nj = 0; nj < 4; nj++)
                    #pragma unroll
                    for (int hf = 0; hf < 2; hf++) {
                        MMA_BF16(c[mi][nj * 2 + hf], ah[mi],
                                 bh[nj][hf * 2], bh[nj][hf * 2 + 1]);
                        MMA_BF16(c[mi][nj * 2 + hf], ah[mi],
                                 bl[nj][hf * 2], bl[nj][hf * 2 + 1]);
                    }
            uint32_t al[4][4];
            #pragma unroll
            for (int mi = 0; mi < 4; mi++)
                LDSM_X4(al[mi], aL + (a_row + mi * 16) * 80 + akoff);
            #pragma unroll
            for (int mi = 0; mi < 4; mi++)
                #pragma unroll
                for (int nj = 0; nj < 4; nj++)
                    #pragma unroll
                    for (int hf = 0; hf < 2; hf++)
                        MMA_BF16(c[mi][nj * 2 + hf], al[mi],
                                 bh[nj][hf * 2], bh[nj][hf * 2 + 1]);
        }
        __syncthreads();
    }

    const int er = m0 + wm * 64 + (lane >> 2);
    if (mode == 0) {
        const int ec = n0 + wn * 64 + (lane & 3) * 2;
        #pragma unroll
        for (int mi = 0; mi < 4; mi++) {
            #pragma unroll
            for (int ni = 0; ni < 8; ni++) {
                int row = er + mi * 16;
                int col = ec + ni * 8;
                float2 v0 = make_float2(c[mi][ni][0], c[mi][ni][1]);
                float2 v1 = make_float2(c[mi][ni][2], c[mi][ni][3]);
                if (R) {
                    float2 t0 = *(const float2*)(R + (size_t)row * N + col);
                    float2 t1 = *(const float2*)(R + (size_t)(row + 8) * N + col);
                    v0.x += t0.x; v0.y += t0.y;
                    v1.x += t1.x; v1.y += t1.y;
                }
                *(float2*)(C + (size_t)row * N + col) = v0;
                *(float2*)(C + (size_t)(row + 8) * N + col) = v1;
            }
        }
    } else {
        const int NG = N >> 1;
        const int gc0 = ((n0 + wn * 64) >> 1) + (lane & 3) * 2;
        #pragma unroll
        for (int mi = 0; mi < 4; mi++) {
            #pragma unroll
            for (int ni = 0; ni < 4; ni++) {
                int gcol = gc0 + ni * 8;
                #pragma unroll
                for (int rr = 0; rr < 2; rr++) {
                    int row = er + mi * 16 + rr * 8;
                    float a0 = c[mi][ni][rr * 2 + 0];
                    float a1 = c[mi][ni][rr * 2 + 1];
                    float b0 = c[mi][ni + 4][rr * 2 + 0];
                    float b1 = c[mi][ni + 4][rr * 2 + 1];
                    float g0 = (a0 / (1.f + __expf(-a0))) * b0;
                    float g1 = (a1 / (1.f + __expf(-a1))) * b1;
                    __nv_bfloat16 h0, l0, h1, l1;
                    split1(g0, h0, l0);
                    split1(g1, h1, l1);
                    size_t o = (size_t)row * NG + gcol;
                    *reinterpret_cast<ushort2*>(Ghi + o) =
                        make_ushort2(__bfloat16_as_ushort(h0), __bfloat16_as_ushort(h1));
                    *reinterpret_cast<ushort2*>(Glo + o) =
                        make_ushort2(__bfloat16_as_ushort(l0), __bfloat16_as_ushort(l1));
                }
            }
        }
    }
}

// ---------------------------------------------------------------------------
// MMA flash-attention (unchanged from round 7)
// ---------------------------------------------------------------------------
constexpr int TPITCH = 272;
constexpr int TQB    = 64 * TPITCH;
constexpr int ATT_SMEM = 6 * TQB;

__global__ __launch_bounds__(128, 2) void attn_kernel(
    const __nv_bfloat16* __restrict__ Qh, const __nv_bfloat16* __restrict__ Ql,
    const __nv_bfloat16* __restrict__ Kh, const __nv_bfloat16* __restrict__ Kl,
    const __nv_bfloat16* __restrict__ Vh, const __nv_bfloat16* __restrict__ Vl,
    __nv_bfloat16* __restrict__ Ohi, __nv_bfloat16* __restrict__ Olo)
{
    extern __shared__ __align__(1024) char smem[];
    const uint32_t sb = smem_u32(smem);
    const uint32_t sQh = sb, sQl = sb + TQB, sKh = sb + 2 * TQB,
                   sKl = sb + 3 * TQB, sVh = sb + 4 * TQB, sVl = sb + 5 * TQB;

    const int tid = threadIdx.x;
    const int warp = tid >> 5, lane = tid & 31;
    const int g = lane >> 2, tig = lane & 3;
    const int q0 = ((int)gridDim.x - 1 - (int)blockIdx.x) * 64;
    const int h = blockIdx.y;
    const size_t hcol = (size_t)h * HD;
    const float scale = 0.08838834764831845f;

    #pragma unroll
    for (int i = 0; i < 16; i++) {
        int ch = tid + (i << 7);
        int sp = ch >> 10, row = (ch >> 4) & 63, cc = ch & 15;
        const __nv_bfloat16* src = sp ? Ql : Qh;
        CP_ASYNC16((sp ? sQl : sQh) + row * TPITCH + cc * 16,
                   src + (size_t)(q0 + row) * D + hcol + cc * 8);
    }
    CP_COMMIT();

    float o[16][4];
    #pragma unroll
    for (int i = 0; i < 16; i++)
        #pragma unroll
        for (int e = 0; e < 4; e++) o[i][e] = 0.f;
    float m0 = -1e30f, m1 = -1e30f, l0 = 0.f, l1 = 0.f;

    const int a_addr_row = warp * 16 + (lane & 15);
    const int a_kad = (lane >> 4) << 3;
    const int b_rowoff = (lane & 7) + ((lane & 16) >> 1);
    const int b_kad = (lane & 8);
    const int v_rowoff = (lane & 7) + (lane & 8);
    const int v_coloff = (lane >> 4) << 3;

    for (int t0 = 0; t0 <= q0; t0 += 64) {
        __syncthreads();
        #pragma unroll
        for (int i = 0; i < 32; i++) {
            int ch = tid + (i << 7);
            int arr = ch >> 10, row = (ch >> 4) & 63, cc = ch & 15;
            const __nv_bfloat16* src = (arr == 0) ? Kh : (arr == 1) ? Kl
                                      : (arr == 2) ? Vh : Vl;
            CP_ASYNC16(sKh + arr * TQB + row * TPITCH + cc * 16,
                       src + (size_t)(t0 + row) * D + hcol + cc * 8);
        }
        CP_COMMIT();
        CP_WAIT(0);
        __syncthreads();

        float s[8][4];
        #pragma unroll
        for (int nt = 0; nt < 8; nt++)
            #pragma unroll
            for (int e = 0; e < 4; e++) s[nt][e] = 0.f;

        #pragma unroll
        for (int ks = 0; ks < 8; ks++) {
            uint32_t qa_h[4], qa_l[4];
            const uint32_t qk = (uint32_t)((ks * 16 + a_kad) * 2);
            LDSM_X4(qa_h, sQh + a_addr_row * TPITCH + qk);
            LDSM_X4(qa_l, sQl + a_addr_row * TPITCH + qk);
            #pragma unroll
            for (int np = 0; np < 4; np++) {
                uint32_t kb_h[4], kb_l[4];
                const uint32_t ka = (np * 16 + b_rowoff) * TPITCH
                                  + (uint32_t)((ks * 16 + b_kad) * 2);
                LDSM_X4(kb_h, sKh + ka);
                LDSM_X4(kb_l, sKl + ka);
                #pragma unroll
                for (int hf = 0; hf < 2; hf++) {
                    MMA_BF16(s[np * 2 + hf], qa_h, kb_h[hf * 2], kb_h[hf * 2 + 1]);
                    MMA_BF16(s[np * 2 + hf], qa_h, kb_l[hf * 2], kb_l[hf * 2 + 1]);
                    MMA_BF16(s[np * 2 + hf], qa_l, kb_h[hf * 2], kb_h[hf * 2 + 1]);
                }
            }
        }

        #pragma unroll
        for (int nt = 0; nt < 8; nt++)
            #pragma unroll
            for (int e = 0; e < 4; e++) s[nt][e] *= scale;
        if (t0 == q0) {
            const int r0 = warp * 16 + g, r1 = r0 + 8;
            #pragma unroll
            for (int nt = 0; nt < 8; nt++) {
                int c0 = nt * 8 + 2 * tig, c1 = c0 + 1;
                if (c0 > r0) s[nt][0] = -1e30f;
                if (c1 > r0) s[nt][1] = -1e30f;
                if (c0 > r1) s[nt][2] = -1e30f;
                if (c1 > r1) s[nt][3] = -1e30f;
            }
        }

        float mx0 = -1e30f, mx1 = -1e30f;
        #pragma unroll
        for (int nt = 0; nt < 8; nt++) {
            mx0 = fmaxf(mx0, fmaxf(s[nt][0], s[nt][1]));
            mx1 = fmaxf(mx1, fmaxf(s[nt][2], s[nt][3]));
        }
        mx0 = fmaxf(mx0, __shfl_xor_sync(0xffffffffu, mx0, 1));
        mx0 = fmaxf(mx0, __shfl_xor_sync(0xffffffffu, mx0, 2));
        mx1 = fmaxf(mx1, __shfl_xor_sync(0xffffffffu, mx1, 1));
        mx1 = fmaxf(mx1, __shfl_xor_sync(0xffffffffu, mx1, 2));
        const float m0n = fmaxf(m0, mx0), m1n = fmaxf(m1, mx1);
        const float f0 = __expf(m0 - m0n), f1 = __expf(m1 - m1n);

        float sum0 = 0.f, sum1 = 0.f;
        uint32_t ph01[8], ph23[8], pl01[8], pl23[8];
        #pragma unroll
        for (int nt = 0; nt < 8; nt++) {
            float p0 = __expf(s[nt][0] - m0n);
            float p1 = __expf(s[nt][1] - m0n);
            float p2 = __expf(s[nt][2] - m1n);
            float p3 = __expf(s[nt][3] - m1n);
            sum0 += p0 + p1;
            sum1 += p2 + p3;
            ph01[nt] = pack_bf16(p0, p1);
            ph23[nt] = pack_bf16(p2, p3);
            __nv_bfloat162 h01 = *reinterpret_cast<__nv_bfloat162*>(&ph01[nt]);
            __nv_bfloat162 h23 = *reinterpret_cast<__nv_bfloat162*>(&ph23[nt]);
            pl01[nt] = pack_bf16(p0 - __bfloat162float(h01.x),
                                 p1 - __bfloat162float(h01.y));
            pl23[nt] = pack_bf16(p2 - __bfloat162float(h23.x),
                                 p3 - __bfloat162float(h23.y));
        }
        sum0 += __shfl_xor_sync(0xffffffffu, sum0, 1);
        sum0 += __shfl_xor_sync(0xffffffffu, sum0, 2);
        sum1 += __shfl_xor_sync(0xffffffffu, sum1, 1);
        sum1 += __shfl_xor_sync(0xffffffffu, sum1, 2);
        l0 = l0 * f0 + sum0;
        l1 = l1 * f1 + sum1;
        #pragma unroll
        for (int nt = 0; nt < 16; nt++) {
            o[nt][0] *= f0; o[nt][1] *= f0;
            o[nt][2] *= f1; o[nt][3] *= f1;
        }

        #pragma unroll
        for (int kt = 0; kt < 4; kt++) {
            uint32_t pa_h[4] = {ph01[2 * kt], ph23[2 * kt],
                                ph01[2 * kt + 1], ph23[2 * kt + 1]};
            uint32_t pa_l[4] = {pl01[2 * kt], pl23[2 * kt],
                                pl01[2 * kt + 1], pl23[2 * kt + 1]};
            #pragma unroll
            for (int np = 0; np < 8; np++) {
                uint32_t vb_h[4], vb_l[4];
                const uint32_t va = (kt * 16 + v_rowoff) * TPITCH
                                  + (uint32_t)((np * 16 + v_coloff) * 2);
                LDSM_X4_T(vb_h, sVh + va);
                LDSM_X4_T(vb_l, sVl + va);
                #pragma unroll
                for (int hf = 0; hf < 2; hf++) {
                    MMA_BF16(o[np * 2 + hf], pa_h, vb_h[hf * 2], vb_h[hf * 2 + 1]);
                    MMA_BF16(o[np * 2 + hf], pa_h, vb_l[hf * 2], vb_l[hf * 2 + 1]);
                    MMA_BF16(o[np * 2 + hf], pa_l, vb_h[hf * 2], vb_h[hf * 2 + 1]);
                }
            }
        }
        m0 = m0n; m1 = m1n;
    }

    const float r0 = 1.f / l0, r1 = 1.f / l1;
    const int row0 = q0 + warp * 16 + g;
    #pragma unroll
    for (int nt = 0; nt < 16; nt++) {
        size_t col = hcol + nt * 8 + 2 * tig;
        __nv_bfloat16 h0, lo0, h1, lo1;
        split1(o[nt][0] * r0, h0, lo0);
        split1(o[nt][1] * r0, h1, lo1);
        size_t idx0 = (size_t)row0 * D + col;
        *reinterpret_cast<ushort2*>(Ohi + idx0) =
            make_ushort2(__bfloat16_as_ushort(h0), __bfloat16_as_ushort(h1));
        *reinterpret_cast<ushort2*>(Olo + idx0) =
            make_ushort2(__bfloat16_as_ushort(lo0), __bfloat16_as_ushort(lo1));
        split1(o[nt][2] * r1, h0, lo0);
        split1(o[nt][3] * r1, h1, lo1);
        size_t idx1 = (size_t)(row0 + 8) * D + col;
        *reinterpret_cast<ushort2*>(Ohi + idx1) =
            make_ushort2(__bfloat16_as_ushort(h0), __bfloat16_as_ushort(h1));
        *reinterpret_cast<ushort2*>(Olo + idx1) =
            make_ushort2(__bfloat16_as_ushort(lo0), __bfloat16_as_ushort(lo1));
    }
}

// ---------------------------------------------------------------------------
// Launch — QKV GEMM at capture index 3
// ---------------------------------------------------------------------------
extern "C" void kernel_launch(void* const* d_in, const int* in_sizes, int n_in,
                              void* d_out, int out_size)
{
    const float* x    = (const float*)d_in[0];
    const float* fcos = (const float*)d_in[2];
    const float* fsin = (const float*)d_in[3];
    const float* wq   = (const float*)d_in[4];
    const float* wk   = (const float*)d_in[5];
    const float* wv   = (const float*)d_in[6];
    const float* wo   = (const float*)d_in[7];
    const float* w1   = (const float*)d_in[8];
    const float* w2   = (const float*)d_in[9];
    const float* w3   = (const float*)d_in[10];
    const float* anw  = (const float*)d_in[11];
    const float* fnw  = (const float*)d_in[12];
    float* out = (float*)d_out;

    float *qkv, *x1;
    __nv_bfloat16 *nxh, *nxl, *aoh, *aol, *gh, *gl;
    __nv_bfloat16 *qh, *ql, *kh, *kl, *vh, *vl;
    __nv_bfloat16 *wqkvh, *wqkvl, *woh, *wol, *w13h, *w13l, *w2h, *w2l;

    cudaGetSymbolAddress((void**)&qkv, g_qkv);
    cudaGetSymbolAddress((void**)&x1, g_x1);
    cudaGetSymbolAddress((void**)&nxh, g_nx_hi);
    cudaGetSymbolAddress((void**)&nxl, g_nx_lo);
    cudaGetSymbolAddress((void**)&aoh, g_ao_hi);
    cudaGetSymbolAddress((void**)&aol, g_ao_lo);
    cudaGetSymbolAddress((void**)&gh, g_g_hi);
    cudaGetSymbolAddress((void**)&gl, g_g_lo);
    cudaGetSymbolAddress((void**)&qh, g_q_hi);
    cudaGetSymbolAddress((void**)&ql, g_q_lo);
    cudaGetSymbolAddress((void**)&kh, g_k_hi);
    cudaGetSymbolAddress((void**)&kl, g_k_lo);
    cudaGetSymbolAddress((void**)&vh, g_v_hi);
    cudaGetSymbolAddress((void**)&vl, g_v_lo);
    cudaGetSymbolAddress((void**)&wqkvh, g_wqkvT_hi);
    cudaGetSymbolAddress((void**)&wqkvl, g_wqkvT_lo);
    cudaGetSymbolAddress((void**)&woh, g_woT_hi);
    cudaGetSymbolAddress((void**)&wol, g_woT_lo);
    cudaGetSymbolAddress((void**)&w13h, g_w13T_hi);
    cudaGetSymbolAddress((void**)&w13l, g_w13T_lo);
    cudaGetSymbolAddress((void**)&w2h, g_w2T_hi);
    cudaGetSymbolAddress((void**)&w2l, g_w2T_lo);

    cudaFuncSetAttribute(gemm3_kernel, cudaFuncAttributeMaxDynamicSharedMemorySize,
                         GEMM_SMEM);
    cudaFuncSetAttribute(attn_kernel, cudaFuncAttributeMaxDynamicSharedMemorySize,
                         ATT_SMEM);

    dim3 tb(32, 8);
    // [0] fused QKV weight transpose
    transpose_qkv_kernel<<<dim3(D / 32, D / 32, 3), tb>>>(wq, wk, wv, wqkvh, wqkvl);
    // [1] attn rmsnorm
    rmsnorm_split_kernel<<<S, 256>>>(x, anw, nxh, nxl);
    // [2] wo transpose
    transpose_split_kernel<<<dim3(D / 32, D / 32), tb>>>(wo, woh, wol, D, D, 0);
    // [3] QKV GEMM  <-- ncu capture target
    gemm3_kernel<<<dim3(QKVN / 256, S / 128), 256, GEMM_SMEM>>>(
        nxh, nxl, wqkvh, wqkvl, nullptr, qkv, nullptr, nullptr, QKVN, D, 0);
    // [4] rope + split
    rope_split_kernel<<<(S * H * 64) / 256, 256>>>(qkv, fcos, fsin,
                                                   qh, ql, kh, kl, vh, vl);
    // [5] attention
    attn_kernel<<<dim3(S / 64, H), 128, ATT_SMEM>>>(qh, ql, kh, kl, vh, vl,
                                                    aoh, aol);
    // [6-8] remaining weight transposes
    transpose_split_kernel<<<dim3(FFI / 32, D / 32), tb>>>(w1, w13h, w13l, D, FFI, 1);
    transpose_split_kernel<<<dim3(FFI / 32, D / 32), tb>>>(w3, w13h, w13l, D, FFI, 2);
    transpose_split_kernel<<<dim3(D / 32, FFI / 32), tb>>>(w2, w2h, w2l, FFI, D, 0);
    // [9] O projection + residual
    gemm3_kernel<<<dim3(D / 256, S / 128), 256, GEMM_SMEM>>>(
        aoh, aol, woh, wol, x, x1, nullptr, nullptr, D, D, 0);
    // [10] ffn rmsnorm
    rmsnorm_split_kernel<<<S, 256>>>(x1, fnw, nxh, nxl);
    // [11] fused w13 GEMM + silu-gate + split
    gemm3_kernel<<<dim3(W13N / 256, S / 128), 256, GEMM_SMEM>>>(
        nxh, nxl, w13h, w13l, nullptr, nullptr, gh, gl, W13N, D, 1);
    // [12] down projection + residual -> out
    gemm3_kernel<<<dim3(D / 256, S / 128), 256, GEMM_SMEM>>>(
        gh, gl, w2h, w2l, x1, out, nullptr, nullptr, D, FFI, 0);
}

// round 10
// speedup vs baseline: 1.0017x; 1.0017x over previous
#include <cuda_runtime.h>
#include <cuda_bf16.h>
#include <cstdint>
#include <math.h>

#define S 2048
#define D 2048
#define H 16
#define HD 128
#define FFI 8192
#define EPS 1e-5f
#define QKVN 6144
#define W13N 16384

// ---------------------------------------------------------------------------
// Static device scratch
// ---------------------------------------------------------------------------
__device__ float g_qkv[S * QKVN];     // [S, 6144] = Q | K | V (fp32, pre-rope)
__device__ float g_x1[S * D];

__device__ __nv_bfloat16 g_nx_hi[S * D],  g_nx_lo[S * D];
__device__ __nv_bfloat16 g_ao_hi[S * D],  g_ao_lo[S * D];
__device__ __nv_bfloat16 g_g_hi[S * FFI], g_g_lo[S * FFI];

// roped + split Q/K and split V, [S, D] bf16
__device__ __nv_bfloat16 g_q_hi[S * D], g_q_lo[S * D];
__device__ __nv_bfloat16 g_k_hi[S * D], g_k_lo[S * D];
__device__ __nv_bfloat16 g_v_hi[S * D], g_v_lo[S * D];

// packed transposed+split weights, [N, K] bf16
__device__ __nv_bfloat16 g_wqkvT_hi[QKVN * D], g_wqkvT_lo[QKVN * D];
__device__ __nv_bfloat16 g_woT_hi[D * D],      g_woT_lo[D * D];
__device__ __nv_bfloat16 g_w13T_hi[W13N * D],  g_w13T_lo[W13N * D];
__device__ __nv_bfloat16 g_w2T_hi[D * FFI],    g_w2T_lo[D * FFI];

// ---------------------------------------------------------------------------
// PTX helpers (baseline sm_80+, compile for compute_103)
// ---------------------------------------------------------------------------
__device__ __forceinline__ uint32_t smem_u32(const void* p) {
    uint32_t a;
    asm("{ .reg .u64 t; cvta.to.shared.u64 t, %1; cvt.u32.u64 %0, t; }"
        : "=r"(a) : "l"(p));
    return a;
}
#define CP_ASYNC16(dst, src) \
    asm volatile("cp.async.cg.shared.global [%0], [%1], 16;" \
                 :: "r"(dst), "l"(src) : "memory")
#define CP_COMMIT() asm volatile("cp.async.commit_group;" ::: "memory")
#define CP_WAIT(n)  asm volatile("cp.async.wait_group %0;" :: "n"(n) : "memory")

#define LDSM_X4(r, addr) \
    asm volatile("ldmatrix.sync.aligned.m8n8.x4.shared.b16 {%0,%1,%2,%3}, [%4];" \
        : "=r"((r)[0]), "=r"((r)[1]), "=r"((r)[2]), "=r"((r)[3]) : "r"(addr))

#define LDSM_X4_T(r, addr) \
    asm volatile("ldmatrix.sync.aligned.m8n8.x4.trans.shared.b16 {%0,%1,%2,%3}, [%4];" \
        : "=r"((r)[0]), "=r"((r)[1]), "=r"((r)[2]), "=r"((r)[3]) : "r"(addr))

#define MMA_BF16(c, a, b0, b1) \
    asm volatile("mma.sync.aligned.m16n8k16.row.col.f32.bf16.bf16.f32 " \
        "{%0,%1,%2,%3}, {%4,%5,%6,%7}, {%8,%9}, {%0,%1,%2,%3};" \
        : "+f"((c)[0]), "+f"((c)[1]), "+f"((c)[2]), "+f"((c)[3]) \
        : "r"((a)[0]), "r"((a)[1]), "r"((a)[2]), "r"((a)[3]), "r"(b0), "r"(b1))

// ---------------------------------------------------------------------------
// fp32 -> bf16 hi/lo split helpers
// ---------------------------------------------------------------------------
__device__ __forceinline__ void split1(float x, __nv_bfloat16& h, __nv_bfloat16& l) {
    h = __float2bfloat16_rn(x);
    l = __float2bfloat16_rn(x - __bfloat162float(h));
}
__device__ __forceinline__ uint32_t pack_bf16(float a, float b) {
    __nv_bfloat162 t;
    t.x = __float2bfloat16_rn(a);
    t.y = __float2bfloat16_rn(b);
    return *reinterpret_cast<uint32_t*>(&t);
}
__device__ __forceinline__ void split_store4(__nv_bfloat16* hi, __nv_bfloat16* lo,
                                             size_t idx, float4 y) {
    __nv_bfloat16 h0, h1, h2, h3, l0, l1, l2, l3;
    split1(y.x, h0, l0); split1(y.y, h1, l1);
    split1(y.z, h2, l2); split1(y.w, h3, l3);
    ushort4 hv = make_ushort4(__bfloat16_as_ushort(h0), __bfloat16_as_ushort(h1),
                              __bfloat16_as_ushort(h2), __bfloat16_as_ushort(h3));
    ushort4 lv = make_ushort4(__bfloat16_as_ushort(l0), __bfloat16_as_ushort(l1),
                              __bfloat16_as_ushort(l2), __bfloat16_as_ushort(l3));
    *reinterpret_cast<ushort4*>(hi + idx) = hv;
    *reinterpret_cast<ushort4*>(lo + idx) = lv;
}
__device__ __forceinline__ void split_store1(__nv_bfloat16* hi, __nv_bfloat16* lo,
                                             size_t idx, float v) {
    __nv_bfloat16 h, l;
    split1(v, h, l);
    hi[idx] = h; lo[idx] = l;
}

// ---------------------------------------------------------------------------
// Fused QKV weight transpose + split: blockIdx.z selects wq/wk/wv
// in [K,N] fp32 -> out rows [z*D .. z*D+N) of [QKVN, K] bf16 hi/lo
// ---------------------------------------------------------------------------
__global__ __launch_bounds__(256) void transpose_qkv_kernel(
    const float* __restrict__ wq, const float* __restrict__ wk,
    const float* __restrict__ wv,
    __nv_bfloat16* __restrict__ ohi, __nv_bfloat16* __restrict__ olo)
{
    __shared__ float t[32][33];
    const float* in = (blockIdx.z == 0) ? wq : (blockIdx.z == 1) ? wk : wv;
    const size_t obase = (size_t)blockIdx.z * D * D;
    int n0 = blockIdx.x * 32, k0 = blockIdx.y * 32;
    int tx = threadIdx.x, ty = threadIdx.y;
    #pragma unroll
    for (int j = 0; j < 4; j++)
        t[ty + 8 * j][tx] = in[(size_t)(k0 + ty + 8 * j) * D + n0 + tx];
    __syncthreads();
    #pragma unroll
    for (int j = 0; j < 4; j++) {
        float v = t[tx][ty + 8 * j];
        size_t o = obase + (size_t)(n0 + ty + 8 * j) * D + k0 + tx;
        __nv_bfloat16 h, l;
        split1(v, h, l);
        ohi[o] = h; olo[o] = l;
    }
}

// ---------------------------------------------------------------------------
// Generic weight transpose + split (remap 1/2 = w1/w3 32-col interleave)
// ---------------------------------------------------------------------------
__global__ __launch_bounds__(256) void transpose_split_kernel(
    const float* __restrict__ in, __nv_bfloat16* __restrict__ ohi,
    __nv_bfloat16* __restrict__ olo, int K, int N, int remap)
{
    __shared__ float t[32][33];
    int n0 = blockIdx.x * 32, k0 = blockIdx.y * 32;
    int tx = threadIdx.x, ty = threadIdx.y;
    #pragma unroll
    for (int j = 0; j < 4; j++)
        t[ty + 8 * j][tx] = in[(size_t)(k0 + ty + 8 * j) * N + n0 + tx];
    __syncthreads();
    #pragma unroll
    for (int j = 0; j < 4; j++) {
        float v = t[tx][ty + 8 * j];
        int n = n0 + ty + 8 * j;
        int outrow = (remap == 0) ? n
                   : ((n >> 5) * 64 + (n & 31) + ((remap == 2) ? 32 : 0));
        size_t o = (size_t)outrow * K + k0 + tx;
        __nv_bfloat16 h, l;
        split1(v, h, l);
        ohi[o] = h; olo[o] = l;
    }
}

// ---------------------------------------------------------------------------
// RMSNorm with split bf16 output
// ---------------------------------------------------------------------------
__global__ __launch_bounds__(256) void rmsnorm_split_kernel(
    const float* __restrict__ X, const float* __restrict__ W,
    __nv_bfloat16* __restrict__ Yhi, __nv_bfloat16* __restrict__ Ylo)
{
    int row = blockIdx.x;
    const float4* x4 = (const float4*)(X + (size_t)row * D);
    const float4* w4 = (const float4*)W;

    float ss = 0.f;
    #pragma unroll 2
    for (int i = threadIdx.x; i < D / 4; i += 256) {
        float4 v = x4[i];
        ss += v.x * v.x + v.y * v.y + v.z * v.z + v.w * v.w;
    }
    #pragma unroll
    for (int o = 16; o; o >>= 1) ss += __shfl_xor_sync(0xffffffffu, ss, o);
    __shared__ float red[8];
    __shared__ float s_inv;
    if ((threadIdx.x & 31) == 0) red[threadIdx.x >> 5] = ss;
    __syncthreads();
    if (threadIdx.x == 0) {
        float t = red[0] + red[1] + red[2] + red[3] + red[4] + red[5] + red[6] + red[7];
        s_inv = rsqrtf(t / (float)D + EPS);
    }
    __syncthreads();
    float inv = s_inv;
    #pragma unroll 2
    for (int i = threadIdx.x; i < D / 4; i += 256) {
        float4 v = x4[i];
        float4 w = w4[i];
        float4 y = make_float4(w.x * (v.x * inv), w.y * (v.y * inv),
                               w.z * (v.z * inv), w.w * (v.w * inv));
        split_store4(Yhi, Ylo, (size_t)row * D + i * 4, y);
    }
}

// ---------------------------------------------------------------------------
// RoPE + split: fp32 packed QKV -> bf16 hi/lo Q(roped), K(roped), V
// ---------------------------------------------------------------------------
__global__ __launch_bounds__(256) void rope_split_kernel(
    const float* __restrict__ QKV,
    const float* __restrict__ cosb, const float* __restrict__ sinb,
    __nv_bfloat16* __restrict__ qh, __nv_bfloat16* __restrict__ ql,
    __nv_bfloat16* __restrict__ kh, __nv_bfloat16* __restrict__ kl,
    __nv_bfloat16* __restrict__ vh, __nv_bfloat16* __restrict__ vl)
{
    int idx = blockIdx.x * blockDim.x + threadIdx.x;
    int d = idx & 63;
    int h = (idx >> 6) & (H - 1);
    int s = idx >> 10;
    size_t ib = (size_t)s * QKVN + (size_t)h * HD;
    size_t ob = (size_t)s * D + (size_t)h * HD;
    float c = cosb[s * HD + d];
    float sn = sinb[s * HD + d];

    float q0 = QKV[ib + d], q1 = QKV[ib + d + 64];
    split_store1(qh, ql, ob + d,      q0 * c - q1 * sn);
    split_store1(qh, ql, ob + d + 64, q1 * c + q0 * sn);

    float k0 = QKV[ib + D + d], k1 = QKV[ib + D + d + 64];
    split_store1(kh, kl, ob + d,      k0 * c - k1 * sn);
    split_store1(kh, kl, ob + d + 64, k1 * c + k0 * sn);

    float v0 = QKV[ib + 2 * D + d], v1 = QKV[ib + 2 * D + d + 64];
    split_store1(vh, vl, ob + d,      v0);
    split_store1(vh, vl, ob + d + 64, v1);
}

// ---------------------------------------------------------------------------
// HMMA bf16x3 GEMM + L2 wave swizzle (group of 4 N-tiles)
// ---------------------------------------------------------------------------
constexpr int A_TILE = 128 * 40 * 2;
constexpr int B_TILE = 256 * 40 * 2;
constexpr int STAGE  = 2 * A_TILE + 2 * B_TILE;
constexpr int GEMM_SMEM = 3 * STAGE;

__global__ __launch_bounds__(256, 1) void gemm3_kernel(
    const __nv_bfloat16* __restrict__ Ahi, const __nv_bfloat16* __restrict__ Alo,
    const __nv_bfloat16* __restrict__ Bhi, const __nv_bfloat16* __restrict__ Blo,
    const float* __restrict__ R, float* __restrict__ C,
    __nv_bfloat16* __restrict__ Ghi, __nv_bfloat16* __restrict__ Glo,
    int N, int K, int mode)
{
    extern __shared__ __align__(1024) char smem[];
    const uint32_t sb = smem_u32(smem);
    const int tid = threadIdx.x;
    const int warp = tid >> 5, lane = tid & 31;
    const int wm = warp >> 2, wn = warp & 3;

    const int lin = blockIdx.y * gridDim.x + blockIdx.x;
    const int gsz = 4 * gridDim.y;
    const int grp = lin / gsz, within = lin % gsz;
    const int m0 = (within >> 2) * 128;
    const int n0 = (grp * 4 + (within & 3)) * 256;

    auto load_stage = [&](int st, int k0) {
        const uint32_t base = sb + st * STAGE;
        #pragma unroll
        for (int i = 0; i < 4; i++) {
            int ch = tid + (i << 8);
            int sp = ch >> 9, row = (ch >> 2) & 127, c = ch & 3;
            const __nv_bfloat16* src = sp ? Alo : Ahi;
            CP_ASYNC16(base + sp * A_TILE + row * 80 + c * 16,
                       src + (size_t)(m0 + row) * K + k0 + c * 8);
        }
        #pragma unroll
        for (int i = 0; i < 8; i++) {
            int ch = tid + (i << 8);
            int sp = ch >> 10, row = (ch >> 2) & 255, c = ch & 3;
            const __nv_bfloat16* src = sp ? Blo : Bhi;
            CP_ASYNC16(base + 2 * A_TILE + sp * B_TILE + row * 80 + c * 16,
                       src + (size_t)(n0 + row) * K + k0 + c * 8);
        }
    };

    float c[4][8][4];
    #pragma unroll
    for (int i = 0; i < 4; i++)
        #pragma unroll
        for (int j = 0; j < 8; j++)
            #pragma unroll
            for (int q = 0; q < 4; q++) c[i][j][q] = 0.f;

    const int a_row = wm * 64 + (lane & 15);
    const int a_kad = (lane >> 4) << 3;
    const int b_row = wn * 64 + (lane & 7) + ((lane & 16) >> 1);
    const int b_kad = (lane & 8);

    const int nc = K >> 5;
    load_stage(0, 0);
    CP_COMMIT();
    load_stage(1, 32);
    CP_COMMIT();

    for (int ci = 0; ci < nc; ci++) {
        if (ci == nc - 1) { CP_WAIT(0); } else { CP_WAIT(1); }
        __syncthreads();
        if (ci + 2 < nc) { load_stage((ci + 2) % 3, (ci + 2) << 5); CP_COMMIT(); }

        const uint32_t base = sb + (ci % 3) * STAGE;
        const uint32_t aH = base, aL = base + A_TILE;
        const uint32_t bH = base + 2 * A_TILE, bL = bH + B_TILE;

        #pragma unroll
        for (int kk = 0; kk < 32; kk += 16) {
            uint32_t ah[4][4], bh[4][4], bl[4][4];
            const uint32_t akoff = (uint32_t)((kk + a_kad) * 2);
            const uint32_t bkoff = (uint32_t)((kk + b_kad) * 2);
            #pragma unroll
            for (int mi = 0; mi < 4; mi++)
                LDSM_X4(ah[mi], aH + (a_row + mi * 16) * 80 + akoff);
            #pragma unroll
            for (int nj = 0; nj < 4; nj++) {
                LDSM_X4(bh[nj], bH + (b_row + nj * 16) * 80 + bkoff);
                LDSM_X4(bl[nj], bL + (b_row + nj * 16) * 80 + bkoff);
            }
            #pragma unroll
            for (int mi = 0; mi < 4; mi++)
                #pragma unroll
                for (int nj = 0; nj < 4; nj++)
                    #pragma unroll
                    for (int hf = 0; hf < 2; hf++) {
                        MMA_BF16(c[mi][nj * 2 + hf], ah[mi],
                                 bh[nj][hf * 2], bh[nj][hf * 2 + 1]);
                        MMA_BF16(c[mi][nj * 2 + hf], ah[mi],
                                 bl[nj][hf * 2], bl[nj][hf * 2 + 1]);
                    }
            uint32_t al[4][4];
            #pragma unroll
            for (int mi = 0; mi < 4; mi++)
                LDSM_X4(al[mi], aL + (a_row + mi * 16) * 80 + akoff);
            #pragma unroll
            for (int mi = 0; mi < 4; mi++)
                #pragma unroll
                for (int nj = 0; nj < 4; nj++)
                    #pragma unroll
                    for (int hf = 0; hf < 2; hf++)
                        MMA_BF16(c[mi][nj * 2 + hf], al[mi],
                                 bh[nj][hf * 2], bh[nj][hf * 2 + 1]);
        }
        __syncthreads();
    }

    const int er = m0 + wm * 64 + (lane >> 2);
    if (mode == 0) {
        const int ec = n0 + wn * 64 + (lane & 3) * 2;
        #pragma unroll
        for (int mi = 0; mi < 4; mi++) {
            #pragma unroll
            for (int ni = 0; ni < 8; ni++) {
                int row = er + mi * 16;
                int col = ec + ni * 8;
                float2 v0 = make_float2(c[mi][ni][0], c[mi][ni][1]);
                float2 v1 = make_float2(c[mi][ni][2], c[mi][ni][3]);
                if (R) {
                    float2 t0 = *(const float2*)(R + (size_t)row * N + col);
                    float2 t1 = *(const float2*)(R + (size_t)(row + 8) * N + col);
                    v0.x += t0.x; v0.y += t0.y;
                    v1.x += t1.x; v1.y += t1.y;
                }
                *(float2*)(C + (size_t)row * N + col) = v0;
                *(float2*)(C + (size_t)(row + 8) * N + col) = v1;
            }
        }
    } else {
        const int NG = N >> 1;
        const int gc0 = ((n0 + wn * 64) >> 1) + (lane & 3) * 2;
        #pragma unroll
        for (int mi = 0; mi < 4; mi++) {
            #pragma unroll
            for (int ni = 0; ni < 4; ni++) {
                int gcol = gc0 + ni * 8;
                #pragma unroll
                for (int rr = 0; rr < 2; rr++) {
                    int row = er + mi * 16 + rr * 8;
                    float a0 = c[mi][ni][rr * 2 + 0];
                    float a1 = c[mi][ni][rr * 2 + 1];
                    float b0 = c[mi][ni + 4][rr * 2 + 0];
                    float b1 = c[mi][ni + 4][rr * 2 + 1];
                    float g0 = (a0 / (1.f + __expf(-a0))) * b0;
                    float g1 = (a1 / (1.f + __expf(-a1))) * b1;
                    __nv_bfloat16 h0, l0, h1, l1;
                    split1(g0, h0, l0);
                    split1(g1, h1, l1);
                    size_t o = (size_t)row * NG + gcol;
                    *reinterpret_cast<ushort2*>(Ghi + o) =
                        make_ushort2(__bfloat16_as_ushort(h0), __bfloat16_as_ushort(h1));
                    *reinterpret_cast<ushort2*>(Glo + o) =
                        make_ushort2(__bfloat16_as_ushort(l0), __bfloat16_as_ushort(l1));
                }
            }
        }
    }
}

// ---------------------------------------------------------------------------
// MMA flash-attention (unchanged from round 7)
// ---------------------------------------------------------------------------
constexpr int TPITCH = 272;
constexpr int TQB    = 64 * TPITCH;
constexpr int ATT_SMEM = 6 * TQB;

__global__ __launch_bounds__(128, 2) void attn_kernel(
    const __nv_bfloat16* __restrict__ Qh, const __nv_bfloat16* __restrict__ Ql,
    const __nv_bfloat16* __restrict__ Kh, const __nv_bfloat16* __restrict__ Kl,
    const __nv_bfloat16* __restrict__ Vh, const __nv_bfloat16* __restrict__ Vl,
    __nv_bfloat16* __restrict__ Ohi, __nv_bfloat16* __restrict__ Olo)
{
    extern __shared__ __align__(1024) char smem[];
    const uint32_t sb = smem_u32(smem);
    const uint32_t sQh = sb, sQl = sb + TQB, sKh = sb + 2 * TQB,
                   sKl = sb + 3 * TQB, sVh = sb + 4 * TQB, sVl = sb + 5 * TQB;

    const int tid = threadIdx.x;
    const int warp = tid >> 5, lane = tid & 31;
    const int g = lane >> 2, tig = lane & 3;
    const int q0 = ((int)gridDim.x - 1 - (int)blockIdx.x) * 64;
    const int h = blockIdx.y;
    const size_t hcol = (size_t)h * HD;
    const float scale = 0.08838834764831845f;

    #pragma unroll
    for (int i = 0; i < 16; i++) {
        int ch = tid + (i << 7);
        int sp = ch >> 10, row = (ch >> 4) & 63, cc = ch & 15;
        const __nv_bfloat16* src = sp ? Ql : Qh;
        CP_ASYNC16((sp ? sQl : sQh) + row * TPITCH + cc * 16,
                   src + (size_t)(q0 + row) * D + hcol + cc * 8);
    }
    CP_COMMIT();

    float o[16][4];
    #pragma unroll
    for (int i = 0; i < 16; i++)
        #pragma unroll
        for (int e = 0; e < 4; e++) o[i][e] = 0.f;
    float m0 = -1e30f, m1 = -1e30f, l0 = 0.f, l1 = 0.f;

    const int a_addr_row = warp * 16 + (lane & 15);
    const int a_kad = (lane >> 4) << 3;
    const int b_rowoff = (lane & 7) + ((lane & 16) >> 1);
    const int b_kad = (lane & 8);
    const int v_rowoff = (lane & 7) + (lane & 8);
    const int v_coloff = (lane >> 4) << 3;

    for (int t0 = 0; t0 <= q0; t0 += 64) {
        __syncthreads();
        #pragma unroll
        for (int i = 0; i < 32; i++) {
            int ch = tid + (i << 7);
            int arr = ch >> 10, row = (ch >> 4) & 63, cc = ch & 15;
            const __nv_bfloat16* src = (arr == 0) ? Kh : (arr == 1) ? Kl
                                      : (arr == 2) ? Vh : Vl;
            CP_ASYNC16(sKh + arr * TQB + row * TPITCH + cc * 16,
                       src + (size_t)(t0 + row) * D + hcol + cc * 8);
        }
        CP_COMMIT();
        CP_WAIT(0);
        __syncthreads();

        float s[8][4];
        #pragma unroll
        for (int nt = 0; nt < 8; nt++)
            #pragma unroll
            for (int e = 0; e < 4; e++) s[nt][e] = 0.f;

        #pragma unroll
        for (int ks = 0; ks < 8; ks++) {
            uint32_t qa_h[4], qa_l[4];
            const uint32_t qk = (uint32_t)((ks * 16 + a_kad) * 2);
            LDSM_X4(qa_h, sQh + a_addr_row * TPITCH + qk);
            LDSM_X4(qa_l, sQl + a_addr_row * TPITCH + qk);
            #pragma unroll
            for (int np = 0; np < 4; np++) {
                uint32_t kb_h[4], kb_l[4];
                const uint32_t ka = (np * 16 + b_rowoff) * TPITCH
                                  + (uint32_t)((ks * 16 + b_kad) * 2);
                LDSM_X4(kb_h, sKh + ka);
                LDSM_X4(kb_l, sKl + ka);
                #pragma unroll
                for (int hf = 0; hf < 2; hf++) {
                    MMA_BF16(s[np * 2 + hf], qa_h, kb_h[hf * 2], kb_h[hf * 2 + 1]);
                    MMA_BF16(s[np * 2 + hf], qa_h, kb_l[hf * 2], kb_l[hf * 2 + 1]);
                    MMA_BF16(s[np * 2 + hf], qa_l, kb_h[hf * 2], kb_h[hf * 2 + 1]);
                }
            }
        }

        #pragma unroll
        for (int nt = 0; nt < 8; nt++)
            #pragma unroll
            for (int e = 0; e < 4; e++) s[nt][e] *= scale;
        if (t0 == q0) {
            const int r0 = warp * 16 + g, r1 = r0 + 8;
            #pragma unroll
            for (int nt = 0; nt < 8; nt++) {
                int c0 = nt * 8 + 2 * tig, c1 = c0 + 1;
                if (c0 > r0) s[nt][0] = -1e30f;
                if (c1 > r0) s[nt][1] = -1e30f;
                if (c0 > r1) s[nt][2] = -1e30f;
                if (c1 > r1) s[nt][3] = -1e30f;
            }
        }

        float mx0 = -1e30f, mx1 = -1e30f;
        #pragma unroll
        for (int nt = 0; nt < 8; nt++) {
            mx0 = fmaxf(mx0, fmaxf(s[nt][0], s[nt][1]));
            mx1 = fmaxf(mx1, fmaxf(s[nt][2], s[nt][3]));
        }
        mx0 = fmaxf(mx0, __shfl_xor_sync(0xffffffffu, mx0, 1));
        mx0 = fmaxf(mx0, __shfl_xor_sync(0xffffffffu, mx0, 2));
        mx1 = fmaxf(mx1, __shfl_xor_sync(0xffffffffu, mx1, 1));
        mx1 = fmaxf(mx1, __shfl_xor_sync(0xffffffffu, mx1, 2));
        const float m0n = fmaxf(m0, mx0), m1n = fmaxf(m1, mx1);
        const float f0 = __expf(m0 - m0n), f1 = __expf(m1 - m1n);

        float sum0 = 0.f, sum1 = 0.f;
        uint32_t ph01[8], ph23[8], pl01[8], pl23[8];
        #pragma unroll
        for (int nt = 0; nt < 8; nt++) {
            float p0 = __expf(s[nt][0] - m0n);
            float p1 = __expf(s[nt][1] - m0n);
            float p2 = __expf(s[nt][2] - m1n);
            float p3 = __expf(s[nt][3] - m1n);
            sum0 += p0 + p1;
            sum1 += p2 + p3;
            ph01[nt] = pack_bf16(p0, p1);
            ph23[nt] = pack_bf16(p2, p3);
            __nv_bfloat162 h01 = *reinterpret_cast<__nv_bfloat162*>(&ph01[nt]);
            __nv_bfloat162 h23 = *reinterpret_cast<__nv_bfloat162*>(&ph23[nt]);
            pl01[nt] = pack_bf16(p0 - __bfloat162float(h01.x),
                                 p1 - __bfloat162float(h01.y));
            pl23[nt] = pack_bf16(p2 - __bfloat162float(h23.x),
                                 p3 - __bfloat162float(h23.y));
        }
        sum0 += __shfl_xor_sync(0xffffffffu, sum0, 1);
        sum0 += __shfl_xor_sync(0xffffffffu, sum0, 2);
        sum1 += __shfl_xor_sync(0xffffffffu, sum1, 1);
        sum1 += __shfl_xor_sync(0xffffffffu, sum1, 2);
        l0 = l0 * f0 + sum0;
        l1 = l1 * f1 + sum1;
        #pragma unroll
        for (int nt = 0; nt < 16; nt++) {
            o[nt][0] *= f0; o[nt][1] *= f0;
            o[nt][2] *= f1; o[nt][3] *= f1;
        }

        #pragma unroll
        for (int kt = 0; kt < 4; kt++) {
            uint32_t pa_h[4] = {ph01[2 * kt], ph23[2 * kt],
                                ph01[2 * kt + 1], ph23[2 * kt + 1]};
            uint32_t pa_l[4] = {pl01[2 * kt], pl23[2 * kt],
                                pl01[2 * kt + 1], pl23[2 * kt + 1]};
            #pragma unroll
            for (int np = 0; np < 8; np++) {
                uint32_t vb_h[4], vb_l[4];
                const uint32_t va = (kt * 16 + v_rowoff) * TPITCH
                                  + (uint32_t)((np * 16 + v_coloff) * 2);
                LDSM_X4_T(vb_h, sVh + va);
                LDSM_X4_T(vb_l, sVl + va);
                #pragma unroll
                for (int hf = 0; hf < 2; hf++) {
                    MMA_BF16(o[np * 2 + hf], pa_h, vb_h[hf * 2], vb_h[hf * 2 + 1]);
                    MMA_BF16(o[np * 2 + hf], pa_h, vb_l[hf * 2], vb_l[hf * 2 + 1]);
                    MMA_BF16(o[np * 2 + hf], pa_l, vb_h[hf * 2], vb_h[hf * 2 + 1]);
                }
            }
        }
        m0 = m0n; m1 = m1n;
    }

    const float r0 = 1.f / l0, r1 = 1.f / l1;
    const int row0 = q0 + warp * 16 + g;
    #pragma unroll
    for (int nt = 0; nt < 16; nt++) {
        size_t col = hcol + nt * 8 + 2 * tig;
        __nv_bfloat16 h0, lo0, h1, lo1;
        split1(o[nt][0] * r0, h0, lo0);
        split1(o[nt][1] * r0, h1, lo1);
        size_t idx0 = (size_t)row0 * D + col;
        *reinterpret_cast<ushort2*>(Ohi + idx0) =
            make_ushort2(__bfloat16_as_ushort(h0), __bfloat16_as_ushort(h1));
        *reinterpret_cast<ushort2*>(Olo + idx0) =
            make_ushort2(__bfloat16_as_ushort(lo0), __bfloat16_as_ushort(lo1));
        split1(o[nt][2] * r1, h0, lo0);
        split1(o[nt][3] * r1, h1, lo1);
        size_t idx1 = (size_t)(row0 + 8) * D + col;
        *reinterpret_cast<ushort2*>(Ohi + idx1) =
            make_ushort2(__bfloat16_as_ushort(h0), __bfloat16_as_ushort(h1));
        *reinterpret_cast<ushort2*>(Olo + idx1) =
            make_ushort2(__bfloat16_as_ushort(lo0), __bfloat16_as_ushort(lo1));
    }
}

// ---------------------------------------------------------------------------
// Launch — QKV GEMM at capture index 3
// ---------------------------------------------------------------------------
extern "C" void kernel_launch(void* const* d_in, const int* in_sizes, int n_in,
                              void* d_out, int out_size)
{
    const float* x    = (const float*)d_in[0];
    const float* fcos = (const float*)d_in[2];
    const float* fsin = (const float*)d_in[3];
    const float* wq   = (const float*)d_in[4];
    const float* wk   = (const float*)d_in[5];
    const float* wv   = (const float*)d_in[6];
    const float* wo   = (const float*)d_in[7];
    const float* w1   = (const float*)d_in[8];
    const float* w2   = (const float*)d_in[9];
    const float* w3   = (const float*)d_in[10];
    const float* anw  = (const float*)d_in[11];
    const float* fnw  = (const float*)d_in[12];
    float* out = (float*)d_out;

    float *qkv, *x1;
    __nv_bfloat16 *nxh, *nxl, *aoh, *aol, *gh, *gl;
    __nv_bfloat16 *qh, *ql, *kh, *kl, *vh, *vl;
    __nv_bfloat16 *wqkvh, *wqkvl, *woh, *wol, *w13h, *w13l, *w2h, *w2l;

    cudaGetSymbolAddress((void**)&qkv, g_qkv);
    cudaGetSymbolAddress((void**)&x1, g_x1);
    cudaGetSymbolAddress((void**)&nxh, g_nx_hi);
    cudaGetSymbolAddress((void**)&nxl, g_nx_lo);
    cudaGetSymbolAddress((void**)&aoh, g_ao_hi);
    cudaGetSymbolAddress((void**)&aol, g_ao_lo);
    cudaGetSymbolAddress((void**)&gh, g_g_hi);
    cudaGetSymbolAddress((void**)&gl, g_g_lo);
    cudaGetSymbolAddress((void**)&qh, g_q_hi);
    cudaGetSymbolAddress((void**)&ql, g_q_lo);
    cudaGetSymbolAddress((void**)&kh, g_k_hi);
    cudaGetSymbolAddress((void**)&kl, g_k_lo);
    cudaGetSymbolAddress((void**)&vh, g_v_hi);
    cudaGetSymbolAddress((void**)&vl, g_v_lo);
    cudaGetSymbolAddress((void**)&wqkvh, g_wqkvT_hi);
    cudaGetSymbolAddress((void**)&wqkvl, g_wqkvT_lo);
    cudaGetSymbolAddress((void**)&woh, g_woT_hi);
    cudaGetSymbolAddress((void**)&wol, g_woT_lo);
    cudaGetSymbolAddress((void**)&w13h, g_w13T_hi);
    cudaGetSymbolAddress((void**)&w13l, g_w13T_lo);
    cudaGetSymbolAddress((void**)&w2h, g_w2T_hi);
    cudaGetSymbolAddress((void**)&w2l, g_w2T_lo);

    cudaFuncSetAttribute(gemm3_kernel, cudaFuncAttributeMaxDynamicSharedMemorySize,
                         GEMM_SMEM);
    cudaFuncSetAttribute(attn_kernel, cudaFuncAttributeMaxDynamicSharedMemorySize,
                         ATT_SMEM);

    dim3 tb(32, 8);
    // [0] fused QKV weight transpose
    transpose_qkv_kernel<<<dim3(D / 32, D / 32, 3), tb>>>(wq, wk, wv, wqkvh, wqkvl);
    // [1] attn rmsnorm
    rmsnorm_split_kernel<<<S, 256>>>(x, anw, nxh, nxl);
    // [2] wo transpose
    transpose_split_kernel<<<dim3(D / 32, D / 32), tb>>>(wo, woh, wol, D, D, 0);
    // [3] QKV GEMM  <-- ncu capture target
    gemm3_kernel<<<dim3(QKVN / 256, S / 128), 256, GEMM_SMEM>>>(
        nxh, nxl, wqkvh, wqkvl, nullptr, qkv, nullptr, nullptr, QKVN, D, 0);
    // [4] rope + split
    rope_split_kernel<<<(S * H * 64) / 256, 256>>>(qkv, fcos, fsin,
                                                   qh, ql, kh, kl, vh, vl);
    // [5] attention
    attn_kernel<<<dim3(S / 64, H), 128, ATT_SMEM>>>(qh, ql, kh, kl, vh, vl,
                                                    aoh, aol);
    // [6-8] remaining weight transposes
    transpose_split_kernel<<<dim3(FFI / 32, D / 32), tb>>>(w1, w13h, w13l, D, FFI, 1);
    transpose_split_kernel<<<dim3(FFI / 32, D / 32), tb>>>(w3, w13h, w13l, D, FFI, 2);
    transpose_split_kernel<<<dim3(D / 32, FFI / 32), tb>>>(w2, w2h, w2l, FFI, D, 0);
    // [9] O projection + residual
    gemm3_kernel<<<dim3(D / 256, S / 128), 256, GEMM_SMEM>>>(
        aoh, aol, woh, wol, x, x1, nullptr, nullptr, D, D, 0);
    // [10] ffn rmsnorm
    rmsnorm_split_kernel<<<S, 256>>>(x1, fnw, nxh, nxl);
    // [11] fused w13 GEMM + silu-gate + split
    gemm3_kernel<<<dim3(W13N / 256, S / 128), 256, GEMM_SMEM>>>(
        nxh, nxl, w13h, w13l, nullptr, nullptr, gh, gl, W13N, D, 1);
    // [12] down projection + residual -> out
    gemm3_kernel<<<dim3(D / 256, S / 128), 256, GEMM_SMEM>>>(
        gh, gl, w2h, w2l, x1, out, nullptr, nullptr, D, FFI, 0);
}